// round 1
// baseline (speedup 1.0000x reference)
#include <cuda_runtime.h>
#include <cuda_bf16.h>

// Problem dims (fixed for this instance)
#define BB   2
#define SS   64
#define CIN  16
#define HID  32
#define COUT 128          // 4*HID
#define HH   64
#define WW   64
#define NN   (BB*SS)      // 128 conv batch
#define HWELEMS (HH*WW)   // 4096

// 268 MB scratch for conv output g4[n][co][h][w]
__device__ float g4_scratch[(size_t)NN * COUT * HH * WW];

// ---------------------------------------------------------------------------
// packed fp32x2 helpers (sm_100a FFMA2 — only reachable via PTX)
// ---------------------------------------------------------------------------
__device__ __forceinline__ unsigned long long pack2(float lo, float hi) {
    unsigned long long r;
    asm("mov.b64 %0, {%1, %2};" : "=l"(r) : "f"(lo), "f"(hi));
    return r;
}
__device__ __forceinline__ void ffma2(unsigned long long& d,
                                      unsigned long long a,
                                      unsigned long long b) {
    asm("fma.rn.f32x2 %0, %1, %2, %0;" : "+l"(d) : "l"(a), "l"(b));
}
__device__ __forceinline__ float2 unpack2(unsigned long long v) {
    float2 r;
    asm("mov.b64 {%0, %1}, %2;" : "=f"(r.x), "=f"(r.y) : "l"(v));
    return r;
}

// ---------------------------------------------------------------------------
// Conv kernel: direct 3x3, pad 1. Block = 4 h-rows x 64 w for one n.
// 128 threads: thread = (w, tr), tr in {0,1}; each thread owns 2 pixel rows
// and 16 output channels (8 FFMA2 channel-pairs) at a time, 8 channel chunks.
// ---------------------------------------------------------------------------
#define TILE_H   4
#define XS_ROWS  (TILE_H + 2)   // 6
#define XS_COLS  (WW + 2)       // 66
#define XS_ELEMS (CIN * XS_ROWS * XS_COLS)   // 6336 floats
#define WSP_PAD  10             // 9 taps padded to 10 for 16B-aligned v2 loads
#define WSP_ELEMS (CIN * 8 * WSP_PAD)        // 1280 u64

__global__ void __launch_bounds__(128)
conv_gates_kernel(const float* __restrict__ x,
                  const float* __restrict__ Wt,
                  const float* __restrict__ bias)
{
    __shared__ float xs[XS_ELEMS];
    __shared__ unsigned long long wsp[WSP_ELEMS];

    const int n   = blockIdx.y;
    const int h0  = blockIdx.x * TILE_H;
    const int tid = threadIdx.x;

    // ---- load x tile (with halo, zero-padded) ----
    const float* xn = x + (size_t)n * CIN * HWELEMS;
    for (int i = tid; i < XS_ELEMS; i += 128) {
        int col = i % XS_COLS;
        int row = (i / XS_COLS) % XS_ROWS;
        int ci  = i / (XS_COLS * XS_ROWS);
        int gr = h0 + row - 1;
        int gc = col - 1;
        float v = 0.0f;
        if (gr >= 0 && gr < HH && gc >= 0 && gc < WW)
            v = xn[(ci * HH + gr) * WW + gc];
        xs[i] = v;
    }

    const int w  = tid & 63;
    const int r0 = (tid >> 6) * 2;   // 0 or 2

    #pragma unroll 1
    for (int cc = 0; cc < 8; cc++) {
        __syncthreads();
        const int cobase = cc * 16;
        // ---- load paired weights: wsp[ci][cop][tap] = (W[co0], W[co0+1]) ----
        for (int i = tid; i < WSP_ELEMS; i += 128) {
            int tap = i % WSP_PAD;
            int cop = (i / WSP_PAD) & 7;
            int ci  = i / (WSP_PAD * 8);
            unsigned long long v = 0ull;
            if (tap < 9) {
                float lo = Wt[(((cobase + 2 * cop)     * CIN + ci) * 9) + tap];
                float hi = Wt[(((cobase + 2 * cop + 1) * CIN + ci) * 9) + tap];
                v = pack2(lo, hi);
            }
            wsp[i] = v;
        }
        __syncthreads();

        unsigned long long acc[8][2];
        #pragma unroll
        for (int cop = 0; cop < 8; cop++) { acc[cop][0] = 0ull; acc[cop][1] = 0ull; }

        #pragma unroll 4
        for (int ci = 0; ci < CIN; ci++) {
            // x taps for rows r0..r0+3, cols w..w+2, broadcast into both halves
            unsigned long long xv[4][3];
            #pragma unroll
            for (int rr = 0; rr < 4; rr++)
                #pragma unroll
                for (int kc = 0; kc < 3; kc++) {
                    float v = xs[(ci * XS_ROWS + (r0 + rr)) * XS_COLS + (w + kc)];
                    xv[rr][kc] = pack2(v, v);
                }
            #pragma unroll
            for (int cop = 0; cop < 8; cop++) {
                const unsigned long long* wt = &wsp[(ci * 8 + cop) * WSP_PAD];
                unsigned long long wr[9];
                // vectorized smem loads (taps 0..7 as 4x ulonglong2, tap 8 scalar)
                #pragma unroll
                for (int q = 0; q < 4; q++) {
                    ulonglong2 t = *reinterpret_cast<const ulonglong2*>(wt + 2 * q);
                    wr[2 * q]     = t.x;
                    wr[2 * q + 1] = t.y;
                }
                wr[8] = wt[8];
                #pragma unroll
                for (int kh = 0; kh < 3; kh++)
                    #pragma unroll
                    for (int kc = 0; kc < 3; kc++) {
                        ffma2(acc[cop][0], xv[kh][kc],     wr[kh * 3 + kc]);
                        ffma2(acc[cop][1], xv[kh + 1][kc], wr[kh * 3 + kc]);
                    }
            }
        }

        // ---- epilogue: add bias, store to g4 scratch ----
        #pragma unroll
        for (int cop = 0; cop < 8; cop++) {
            const int co0 = cobase + 2 * cop;
            const float b0 = __ldg(&bias[co0]);
            const float b1 = __ldg(&bias[co0 + 1]);
            #pragma unroll
            for (int p = 0; p < 2; p++) {
                float2 v = unpack2(acc[cop][p]);
                const int h = h0 + r0 + p;
                g4_scratch[(((size_t)n * COUT + co0)     * HH + h) * WW + w] = v.x + b0;
                g4_scratch[(((size_t)n * COUT + co0 + 1) * HH + h) * WW + w] = v.y + b1;
            }
        }
    }
}

// ---------------------------------------------------------------------------
// Recurrence: one thread per (b, chan, h, w) sequence. Linear-space stable
// convex recurrence equivalent to the reference's log-space scan:
//   f' = sig(f)/(sig(f)+sig(i)) = (1+e^-i)/(2+e^-i+e^-f),  i' = 1-f'
//   c_t = f'*c_{t-1} + i'*g(cell),   out = sig(o)*c_t
// ---------------------------------------------------------------------------
__device__ __forceinline__ float fsigmoid(float v) {
    return __fdividef(1.0f, 1.0f + __expf(-v));
}

__global__ void __launch_bounds__(256)
lstm_scan_kernel(const float* __restrict__ c0,
                 float* __restrict__ out,
                 float* __restrict__ clast)
{
    const int idx = blockIdx.x * blockDim.x + threadIdx.x;  // 0..262143
    const int hw = idx & 4095;
    const int c  = (idx >> 12) & 31;
    const int b  = idx >> 17;

    float cs = c0[((size_t)b * HID + c) * HWELEMS + hw];
    const float* gp = g4_scratch + ((size_t)b * SS * COUT) * HWELEMS + hw;
    float* op = out + ((size_t)b * SS * HID + c) * HWELEMS + hw;

    #pragma unroll 4
    for (int s = 0; s < SS; s++) {
        const float* gs = gp + (size_t)s * COUT * HWELEMS;
        const float ig = gs[(size_t)(c)      * HWELEMS];
        const float fg = gs[(size_t)(c + 32) * HWELEMS];
        const float og = gs[(size_t)(c + 64) * HWELEMS];
        const float cg = gs[(size_t)(c + 96) * HWELEMS];

        const float ei  = __expf(-ig);
        const float ef  = __expf(-fg);
        const float inv = __fdividef(1.0f, 2.0f + ei + ef);
        const float fp  = (1.0f + ei) * inv;   // log-normalized forget gate
        const float ip  = (1.0f + ef) * inv;   // log-normalized input gate
        const float g   = (cg >= 0.0f) ? (cg + 0.5f) : fsigmoid(cg);

        cs = fp * cs + ip * g;
        op[(size_t)s * HID * HWELEMS] = fsigmoid(og) * cs;
    }
    clast[((size_t)b * HID + c) * HWELEMS + hw] = cs;
}

// ---------------------------------------------------------------------------
extern "C" void kernel_launch(void* const* d_in, const int* in_sizes, int n_in,
                              void* d_out, int out_size)
{
    const float* x  = (const float*)d_in[0];   // (2,64,16,64,64)
    const float* Wt = (const float*)d_in[1];   // (128,16,3,3)
    const float* b  = (const float*)d_in[2];   // (128)
    const float* c0 = (const float*)d_in[3];   // (2,1,32,64,64)

    float* out   = (float*)d_out;                              // (2,64,32,64,64)
    float* clast = out + (size_t)BB * SS * HID * HWELEMS;      // (2,1,32,64,64)

    dim3 cgrid(HH / TILE_H, NN);   // (16, 128)
    conv_gates_kernel<<<cgrid, 128>>>(x, Wt, b);

    const int total = BB * HID * HWELEMS;      // 262144
    lstm_scan_kernel<<<total / 256, 256>>>(c0, out, clast);
}